// round 8
// baseline (speedup 1.0000x reference)
#include <cuda_runtime.h>
#include <cuda_bf16.h>

// ---------------------------------------------------------------------------
// TriplaneEncoder: out[n][c] = sum_{p=0..2} bilinear(C_mat[p], coords_p(n))[c]
// Planes index pairs: p0:(x0,x1), p1:(x0,x2), p2:(x1,x2)  (gx = first, gy = second)
// align_corners=False, zero padding. RES=512, C=32, N=2097152.
//
// Strategy:
//   1) transpose C_mat [3][32][512][512] -> g_T [3][512][512][32]  (pixel-major,
//      128B per pixel => sector-perfect gathers)
//   2) sample kernel: 8 threads per point, each owns 4 channels (float4);
//      per plane per corner one float4 load; lanes 0..7 of a point cover one
//      contiguous 128B pixel record.
// ---------------------------------------------------------------------------

#define RES   512
#define CFEAT 32

// 3 * 512 * 512 * 32 floats = 96 MB scratch (pixel-major table)
__device__ float g_T[3 * RES * RES * CFEAT];

// ---------------------------------------------------------------------------
// Transpose: src [p][c][y][x] -> dst [p][y][x][c], smem-tiled 32c x 32x.
// Block: 32x8 threads. Each block handles one (p, y, xtile).
// grid.x = RES/32 = 16 (xtile), grid.y = RES (y), grid.z = 3 (p)
// ---------------------------------------------------------------------------
__global__ __launch_bounds__(256)
void transpose_kernel(const float* __restrict__ src)
{
    __shared__ float tile[32][33];   // [c][x], padded to kill bank conflicts

    const int p  = blockIdx.z;
    const int y  = blockIdx.y;
    const int x0 = blockIdx.x * 32;
    const int tx = threadIdx.x;      // 0..31
    const int ty = threadIdx.y;      // 0..7

    // Load: 32 channels x 32 x-positions, coalesced along x
    const float* sp = src + ((size_t)p * CFEAT) * (RES * RES) + (size_t)y * RES + x0;
    #pragma unroll
    for (int c = ty; c < 32; c += 8) {
        tile[c][tx] = sp[(size_t)c * (RES * RES) + tx];
    }
    __syncthreads();

    // Store: for each x, 32 consecutive channels; coalesced along c (=tx)
    float* dp = g_T + (((size_t)p * RES + y) * RES + x0) * CFEAT;
    #pragma unroll
    for (int xi = ty; xi < 32; xi += 8) {
        dp[(size_t)xi * CFEAT + tx] = tile[tx][xi];
    }
}

// ---------------------------------------------------------------------------
// Sample kernel: 8 threads per point, thread owns channels [4*sub, 4*sub+4)
// ---------------------------------------------------------------------------
__device__ __forceinline__ void accum_corner(float4& acc, const float* __restrict__ ptr, float w)
{
    float4 v = *reinterpret_cast<const float4*>(ptr);
    acc.x = fmaf(w, v.x, acc.x);
    acc.y = fmaf(w, v.y, acc.y);
    acc.z = fmaf(w, v.z, acc.z);
    acc.w = fmaf(w, v.w, acc.w);
}

__global__ __launch_bounds__(256)
void sample_kernel(const float* __restrict__ x, float* __restrict__ out, int npts)
{
    const int gid = blockIdx.x * blockDim.x + threadIdx.x;
    const int pt  = gid >> 3;
    const int cg  = (gid & 7) * 4;           // channel offset within 32
    if (pt >= npts) return;

    // All 8 lanes of a point read the same 3 floats -> broadcast in L1
    const float c0 = __ldg(x + (size_t)pt * 3 + 0);
    const float c1 = __ldg(x + (size_t)pt * 3 + 1);
    const float c2 = __ldg(x + (size_t)pt * 3 + 2);

    // plane coords (gx indexes W/last axis, gy indexes H)
    float gxs[3] = { c0, c0, c1 };
    float gys[3] = { c1, c2, c2 };

    float4 acc = make_float4(0.f, 0.f, 0.f, 0.f);

    #pragma unroll
    for (int p = 0; p < 3; ++p) {
        // ix = ((gx + 1) * 512 - 1) * 0.5 ; same for iy
        const float ix = ((gxs[p] + 1.0f) * (float)RES - 1.0f) * 0.5f;
        const float iy = ((gys[p] + 1.0f) * (float)RES - 1.0f) * 0.5f;

        const float x0f = floorf(ix);
        const float y0f = floorf(iy);
        const float wx1 = ix - x0f, wx0 = 1.0f - wx1;
        const float wy1 = iy - y0f, wy0 = 1.0f - wy1;

        const int xi0 = (int)x0f;
        const int yi0 = (int)y0f;
        const int xi1 = xi0 + 1;
        const int yi1 = yi0 + 1;

        const float mx0 = (xi0 >= 0 && xi0 <= RES - 1) ? 1.0f : 0.0f;
        const float mx1 = (xi1 >= 0 && xi1 <= RES - 1) ? 1.0f : 0.0f;
        const float my0 = (yi0 >= 0 && yi0 <= RES - 1) ? 1.0f : 0.0f;
        const float my1 = (yi1 >= 0 && yi1 <= RES - 1) ? 1.0f : 0.0f;

        const int xc0 = min(max(xi0, 0), RES - 1);
        const int xc1 = min(max(xi1, 0), RES - 1);
        const int yc0 = min(max(yi0, 0), RES - 1);
        const int yc1 = min(max(yi1, 0), RES - 1);

        const float* Tp = g_T + (size_t)p * (RES * RES * CFEAT) + cg;
        const float* p00 = Tp + ((size_t)yc0 * RES + xc0) * CFEAT;
        const float* p10 = Tp + ((size_t)yc0 * RES + xc1) * CFEAT;
        const float* p01 = Tp + ((size_t)yc1 * RES + xc0) * CFEAT;
        const float* p11 = Tp + ((size_t)yc1 * RES + xc1) * CFEAT;

        accum_corner(acc, p00, wx0 * wy0 * (mx0 * my0));
        accum_corner(acc, p10, wx1 * wy0 * (mx1 * my0));
        accum_corner(acc, p01, wx0 * wy1 * (mx0 * my1));
        accum_corner(acc, p11, wx1 * wy1 * (mx1 * my1));
    }

    // Streaming store: don't let 256MB of output evict the 96MB table from L2
    __stwt(reinterpret_cast<float4*>(out + (size_t)pt * CFEAT + cg), acc);
}

// ---------------------------------------------------------------------------
extern "C" void kernel_launch(void* const* d_in, const int* in_sizes, int n_in,
                              void* d_out, int out_size)
{
    const float* x_in  = (const float*)d_in[0];   // [N, 3]
    const float* c_mat = (const float*)d_in[1];   // [3, 32, 512, 512]
    float* out = (float*)d_out;                   // [N, 32]

    const int npts = in_sizes[0] / 3;

    // 1) layout transform into pixel-major scratch
    dim3 tb(32, 8);
    dim3 tg(RES / 32, RES, 3);
    transpose_kernel<<<tg, tb>>>(c_mat);

    // 2) gather + bilinear blend
    const int threads = 256;
    const long long total = (long long)npts * 8;
    const int blocks = (int)((total + threads - 1) / threads);
    sample_kernel<<<blocks, threads>>>(x_in, out, npts);
}

// round 9
// speedup vs baseline: 1.8705x; 1.8705x over previous
#include <cuda_runtime.h>
#include <cuda_fp16.h>
#include <cuda_bf16.h>

// ---------------------------------------------------------------------------
// TriplaneEncoder: out[n][c] = sum_{p=0..2} bilinear(C_mat[p], coords_p(n))[c]
// Planes: p0:(x0,x1), p1:(x0,x2), p2:(x1,x2); gx = first (W axis), gy = second (H).
// align_corners=False, zero padding. RES=512, C=32, N=2097152.
//
// R8 change: fp16 pixel-major table (48 MB -> L2-resident, halves gather bytes).
//   1) fused transpose+convert: C_mat [3][32][512][512] f32 -> g_Th [3][512][512][32] f16
//   2) sample: 4 threads per point, each owns 8 channels; one LDG.128 (8 halves)
//      per corner per plane; fp32 accumulate; streaming fp32 output stores.
// ---------------------------------------------------------------------------

#define RES   512
#define CFEAT 32

// 3 * 512 * 512 * 32 halves = 48 MB scratch (pixel-major fp16 table)
__device__ __half g_Th[3 * RES * RES * CFEAT];

// ---------------------------------------------------------------------------
// Transpose+convert: src [p][c][y][x] f32 -> dst [p][y][x][c] f16.
// Block 32x8. grid = (16, 512, 3).
// ---------------------------------------------------------------------------
__global__ __launch_bounds__(256)
void transpose_kernel(const float* __restrict__ src)
{
    __shared__ float tile[32][33];   // [c][x], padded

    const int p  = blockIdx.z;
    const int y  = blockIdx.y;
    const int x0 = blockIdx.x * 32;
    const int tx = threadIdx.x;      // 0..31
    const int ty = threadIdx.y;      // 0..7

    const float* sp = src + ((size_t)p * CFEAT) * (RES * RES) + (size_t)y * RES + x0;
    #pragma unroll
    for (int c = ty; c < 32; c += 8) {
        tile[c][tx] = sp[(size_t)c * (RES * RES) + tx];
    }
    __syncthreads();

    __half* dp = g_Th + (((size_t)p * RES + y) * RES + x0) * CFEAT;
    #pragma unroll
    for (int xi = ty; xi < 32; xi += 8) {
        dp[(size_t)xi * CFEAT + tx] = __float2half_rn(tile[tx][xi]);
    }
}

// ---------------------------------------------------------------------------
// Sample kernel: 4 threads per point; thread owns channels [8*sub, 8*sub+8)
// ---------------------------------------------------------------------------
__device__ __forceinline__ void accum_corner8(float acc[8], const __half* __restrict__ ptr, float w)
{
    // 8 halves = 16 bytes, 16B-aligned (cg multiple of 8 halves)
    const uint4 raw = *reinterpret_cast<const uint4*>(ptr);
    const __half2* h2 = reinterpret_cast<const __half2*>(&raw);
    #pragma unroll
    for (int i = 0; i < 4; ++i) {
        float2 f = __half22float2(h2[i]);
        acc[2 * i + 0] = fmaf(w, f.x, acc[2 * i + 0]);
        acc[2 * i + 1] = fmaf(w, f.y, acc[2 * i + 1]);
    }
}

__global__ __launch_bounds__(256)
void sample_kernel(const float* __restrict__ x, float* __restrict__ out, int npts)
{
    const int gid = blockIdx.x * blockDim.x + threadIdx.x;
    const int pt  = gid >> 2;
    const int cg  = (gid & 3) * 8;           // channel offset within 32
    if (pt >= npts) return;

    // 4 lanes of a point read the same 3 floats -> L1 broadcast
    const float c0 = __ldg(x + (size_t)pt * 3 + 0);
    const float c1 = __ldg(x + (size_t)pt * 3 + 1);
    const float c2 = __ldg(x + (size_t)pt * 3 + 2);

    const float gxs[3] = { c0, c0, c1 };
    const float gys[3] = { c1, c2, c2 };

    float acc[8];
    #pragma unroll
    for (int i = 0; i < 8; ++i) acc[i] = 0.0f;

    #pragma unroll
    for (int p = 0; p < 3; ++p) {
        const float ix = ((gxs[p] + 1.0f) * (float)RES - 1.0f) * 0.5f;
        const float iy = ((gys[p] + 1.0f) * (float)RES - 1.0f) * 0.5f;

        const float x0f = floorf(ix);
        const float y0f = floorf(iy);
        const float wx1 = ix - x0f, wx0 = 1.0f - wx1;
        const float wy1 = iy - y0f, wy0 = 1.0f - wy1;

        const int xi0 = (int)x0f;
        const int yi0 = (int)y0f;
        const int xi1 = xi0 + 1;
        const int yi1 = yi0 + 1;

        const float mx0 = (xi0 >= 0 && xi0 <= RES - 1) ? 1.0f : 0.0f;
        const float mx1 = (xi1 >= 0 && xi1 <= RES - 1) ? 1.0f : 0.0f;
        const float my0 = (yi0 >= 0 && yi0 <= RES - 1) ? 1.0f : 0.0f;
        const float my1 = (yi1 >= 0 && yi1 <= RES - 1) ? 1.0f : 0.0f;

        const int xc0 = min(max(xi0, 0), RES - 1);
        const int xc1 = min(max(xi1, 0), RES - 1);
        const int yc0 = min(max(yi0, 0), RES - 1);
        const int yc1 = min(max(yi1, 0), RES - 1);

        const __half* Tp = g_Th + (size_t)p * (RES * RES * CFEAT) + cg;
        const __half* p00 = Tp + ((size_t)yc0 * RES + xc0) * CFEAT;
        const __half* p10 = Tp + ((size_t)yc0 * RES + xc1) * CFEAT;
        const __half* p01 = Tp + ((size_t)yc1 * RES + xc0) * CFEAT;
        const __half* p11 = Tp + ((size_t)yc1 * RES + xc1) * CFEAT;

        accum_corner8(acc, p00, wx0 * wy0 * (mx0 * my0));
        accum_corner8(acc, p10, wx1 * wy0 * (mx1 * my0));
        accum_corner8(acc, p01, wx0 * wy1 * (mx0 * my1));
        accum_corner8(acc, p11, wx1 * wy1 * (mx1 * my1));
    }

    // Streaming stores: 32 B per thread, 128 B per point across 4 lanes.
    float4* o = reinterpret_cast<float4*>(out + (size_t)pt * CFEAT + cg);
    __stwt(o + 0, make_float4(acc[0], acc[1], acc[2], acc[3]));
    __stwt(o + 1, make_float4(acc[4], acc[5], acc[6], acc[7]));
}

// ---------------------------------------------------------------------------
extern "C" void kernel_launch(void* const* d_in, const int* in_sizes, int n_in,
                              void* d_out, int out_size)
{
    const float* x_in  = (const float*)d_in[0];   // [N, 3]
    const float* c_mat = (const float*)d_in[1];   // [3, 32, 512, 512]
    float* out = (float*)d_out;                   // [N, 32]

    const int npts = in_sizes[0] / 3;

    // 1) layout transform + fp16 convert into pixel-major scratch
    dim3 tb(32, 8);
    dim3 tg(RES / 32, RES, 3);
    transpose_kernel<<<tg, tb>>>(c_mat);

    // 2) gather + bilinear blend
    const int threads = 256;
    const long long total = (long long)npts * 4;
    const int blocks = (int)((total + threads - 1) / threads);
    sample_kernel<<<blocks, threads>>>(x_in, out, npts);
}